// round 7
// baseline (speedup 1.0000x reference)
#include <cuda_runtime.h>

#define NN 10000
#define TT 2
#define CC 64
#define HH 4
#define CO 64
#define HC 256
#define EE 160000
#define MROWS (TT*NN)

typedef unsigned long long ull;

// scratch (static device allocations; no cudaMalloc allowed)
__device__ float g_xl[MROWS * HC];
__device__ float g_xr[MROWS * HC];
__device__ float g_mha[MROWS * HC];
__device__ int   g_deg[NN];      // zero-initialized; k_scan re-zeroes after use
__device__ int   g_rowptr[NN + 1];
__device__ int   g_cursor[NN];
__device__ int   g_srcs[EE];

// ---- packed f32x2 helpers (sm_103a FFMA2 path; ptxas never emits this) ----
__device__ __forceinline__ ull pack2(float a, float b) {
    ull r;
    asm("mov.b64 %0, {%1, %2};" : "=l"(r) : "f"(a), "f"(b));
    return r;
}
__device__ __forceinline__ void ffma2(ull& d, ull a, ull b) {
    asm("fma.rn.f32x2 %0, %1, %2, %0;" : "+l"(d) : "l"(a), "l"(b));
}
__device__ __forceinline__ float2 unpack2(ull v) {
    float2 f;
    asm("mov.b64 {%0, %1}, %2;" : "=f"(f.x), "=f"(f.y) : "l"(v));
    return f;
}

__global__ void k_hist(const int* __restrict__ ei) {
    int e = blockIdx.x * blockDim.x + threadIdx.x;
    if (e < EE) atomicAdd(&g_deg[ei[EE + e]], 1);
}

__global__ void __launch_bounds__(1024) k_scan() {
    __shared__ int sc[1024];
    int tid = threadIdx.x;
    const int CH = (NN + 1023) / 1024;  // 10
    int base = tid * CH;
    int local = 0;
    for (int j = 0; j < CH; j++) {
        int idx = base + j;
        if (idx < NN) local += g_deg[idx];
    }
    sc[tid] = local;
    __syncthreads();
    for (int off = 1; off < 1024; off <<= 1) {
        int v = (tid >= off) ? sc[tid - off] : 0;
        __syncthreads();
        sc[tid] += v;
        __syncthreads();
    }
    int run = sc[tid] - local;  // exclusive prefix
    for (int j = 0; j < CH; j++) {
        int idx = base + j;
        if (idx < NN) {
            int d = g_deg[idx];
            g_rowptr[idx] = run;
            g_cursor[idx] = run;
            run += d;
            g_deg[idx] = 0;   // reset for next invocation (replay-deterministic)
        }
    }
    if (tid == 1023) g_rowptr[NN] = sc[1023];
}

__global__ void k_scatter(const int* __restrict__ ei) {
    int e = blockIdx.x * blockDim.x + threadIdx.x;
    if (e < EE) {
        int d = ei[EE + e];
        int s = ei[e];
        int pos = atomicAdd(&g_cursor[d], 1);
        g_srcs[pos] = s;
    }
}

// Dual GEMM with packed FFMA2 over k-pairs.
// 512 threads: c4 = tid&63 (4 cols via float4), rg = tid>>6 (8 groups x 4 rows).
// Each acc holds a k-pair of partial sums; horizontal add at the end.
__global__ void __launch_bounds__(512) k_gemm(
    const float* __restrict__ x,
    const float* __restrict__ Wl, const float* __restrict__ bl,
    const float* __restrict__ Wr, const float* __restrict__ br)
{
    __shared__ __align__(8) float xs[32][64];
    int tid = threadIdx.x;
    int row0 = blockIdx.x * 32;
    for (int i = tid; i < 32 * 64; i += 512) {
        xs[i >> 6][i & 63] = x[(row0 + (i >> 6)) * CC + (i & 63)];
    }
    __syncthreads();
    int c4 = tid & 63;
    int rg = tid >> 6;  // rows rg*4 .. rg*4+3

    ull accl[4][4], accr[4][4];
#pragma unroll
    for (int r = 0; r < 4; r++)
#pragma unroll
        for (int e = 0; e < 4; e++) { accl[r][e] = 0ull; accr[r][e] = 0ull; }

    const float4* Wl4 = (const float4*)Wl;
    const float4* Wr4 = (const float4*)Wr;
#pragma unroll 4
    for (int k = 0; k < 64; k += 2) {
        float4 wl0 = Wl4[k * 64 + c4];
        float4 wl1 = Wl4[(k + 1) * 64 + c4];
        float4 wr0 = Wr4[k * 64 + c4];
        float4 wr1 = Wr4[(k + 1) * 64 + c4];
        ull wlp[4] = { pack2(wl0.x, wl1.x), pack2(wl0.y, wl1.y),
                       pack2(wl0.z, wl1.z), pack2(wl0.w, wl1.w) };
        ull wrp[4] = { pack2(wr0.x, wr1.x), pack2(wr0.y, wr1.y),
                       pack2(wr0.z, wr1.z), pack2(wr0.w, wr1.w) };
#pragma unroll
        for (int r = 0; r < 4; r++) {
            ull xv = *(const ull*)&xs[rg * 4 + r][k];   // {x[k], x[k+1]}
#pragma unroll
            for (int e = 0; e < 4; e++) {
                ffma2(accl[r][e], xv, wlp[e]);
                ffma2(accr[r][e], xv, wrp[e]);
            }
        }
    }

    float4 bl4 = ((const float4*)bl)[c4];
    float4 br4 = ((const float4*)br)[c4];
    float blv[4] = { bl4.x, bl4.y, bl4.z, bl4.w };
    float brv[4] = { br4.x, br4.y, br4.z, br4.w };
#pragma unroll
    for (int r = 0; r < 4; r++) {
        int row = row0 + rg * 4 + r;
        float ol[4], orr[4];
#pragma unroll
        for (int e = 0; e < 4; e++) {
            float2 ul = unpack2(accl[r][e]);
            float2 ur = unpack2(accr[r][e]);
            ol[e] = ul.x + ul.y + blv[e];
            orr[e] = ur.x + ur.y + brv[e];
        }
        ((float4*)g_xl)[row * 64 + c4] = make_float4(ol[0], ol[1], ol[2], ol[3]);
        ((float4*)g_xr)[row * 64 + c4] = make_float4(orr[0], orr[1], orr[2], orr[3]);
    }
}

// GAT aggregation: one WARP per (t, n). Single pass, no-max softmax.
// Lane L owns head (L>>3), dims [(L&7)*8, +8) -> float4 indices 2L, 2L+1.
__device__ __forceinline__ int get_src(int k, int s0, int s1, int base) {
    if (k < 32) return __shfl_sync(0xffffffffu, s0, k);
    if (k < 64) return __shfl_sync(0xffffffffu, s1, k - 32);
    return g_srcs[base + k];
}

__global__ void __launch_bounds__(256) k_agg(
    const float* __restrict__ att,
    const float* __restrict__ bias)
{
    int w = blockIdx.x * 8 + (threadIdx.x >> 5);
    if (w >= MROWS) return;
    int lane = threadIdx.x & 31;
    int n = w % NN;
    int t = w / NN;
    int f4 = lane * 2;

    const float4* xr = (const float4*)&g_xr[w * HC];
    float4 xr0 = xr[f4];
    float4 xr1 = xr[f4 + 1];
    float4 at0 = ((const float4*)att)[f4];
    float4 at1 = ((const float4*)att)[f4 + 1];

    int base = g_rowptr[n];
    int deg = g_rowptr[n + 1] - base;

    int s0 = (lane < deg) ? g_srcs[base + lane] : 0;
    int s1 = (32 + lane < deg) ? g_srcs[base + 32 + lane] : 0;

    float den = 0.f;
    float4 acc0 = make_float4(0.f, 0.f, 0.f, 0.f);
    float4 acc1 = make_float4(0.f, 0.f, 0.f, 0.f);
    int xlbase = t * NN * HC;

    float4 A0, A1, B0, B1;
    if (deg > 0) {
        const float4* xl = (const float4*)&g_xl[xlbase + get_src(0, s0, s1, base) * HC];
        A0 = xl[f4]; A1 = xl[f4 + 1];
    }
    if (deg > 1) {
        const float4* xl = (const float4*)&g_xl[xlbase + get_src(1, s0, s1, base) * HC];
        B0 = xl[f4]; B1 = xl[f4 + 1];
    }

#define AGG_BODY(a0, a1)                                                     \
    {                                                                        \
        float v, p;                                                          \
        v = a0.x + xr0.x; v = fmaxf(v, 0.2f * v); p = v * at0.x;             \
        v = a0.y + xr0.y; v = fmaxf(v, 0.2f * v); p = fmaf(v, at0.y, p);     \
        v = a0.z + xr0.z; v = fmaxf(v, 0.2f * v); p = fmaf(v, at0.z, p);     \
        v = a0.w + xr0.w; v = fmaxf(v, 0.2f * v); p = fmaf(v, at0.w, p);     \
        v = a1.x + xr1.x; v = fmaxf(v, 0.2f * v); p = fmaf(v, at1.x, p);     \
        v = a1.y + xr1.y; v = fmaxf(v, 0.2f * v); p = fmaf(v, at1.y, p);     \
        v = a1.z + xr1.z; v = fmaxf(v, 0.2f * v); p = fmaf(v, at1.z, p);     \
        v = a1.w + xr1.w; v = fmaxf(v, 0.2f * v); p = fmaf(v, at1.w, p);     \
        p += __shfl_xor_sync(0xffffffffu, p, 1);                             \
        p += __shfl_xor_sync(0xffffffffu, p, 2);                             \
        p += __shfl_xor_sync(0xffffffffu, p, 4);                             \
        float e = __expf(p);                                                 \
        den += e;                                                            \
        acc0.x = fmaf(e, a0.x, acc0.x);                                      \
        acc0.y = fmaf(e, a0.y, acc0.y);                                      \
        acc0.z = fmaf(e, a0.z, acc0.z);                                      \
        acc0.w = fmaf(e, a0.w, acc0.w);                                      \
        acc1.x = fmaf(e, a1.x, acc1.x);                                      \
        acc1.y = fmaf(e, a1.y, acc1.y);                                      \
        acc1.z = fmaf(e, a1.z, acc1.z);                                      \
        acc1.w = fmaf(e, a1.w, acc1.w);                                      \
    }

    int k = 0;
    while (k < deg) {
        {
            float4 a0 = A0, a1 = A1;
            if (k + 2 < deg) {
                const float4* xl = (const float4*)&g_xl[xlbase + get_src(k + 2, s0, s1, base) * HC];
                A0 = xl[f4]; A1 = xl[f4 + 1];
            }
            AGG_BODY(a0, a1);
        }
        k++;
        if (k >= deg) break;
        {
            float4 a0 = B0, a1 = B1;
            if (k + 2 < deg) {
                const float4* xl = (const float4*)&g_xl[xlbase + get_src(k + 2, s0, s1, base) * HC];
                B0 = xl[f4]; B1 = xl[f4 + 1];
            }
            AGG_BODY(a0, a1);
        }
        k++;
    }
#undef AGG_BODY

    float inv = (deg > 0) ? 1.0f / den : 0.f;
    const float4* b4 = (const float4*)bias;
    float4 bb0 = b4[f4], bb1 = b4[f4 + 1];
    float4 o0, o1;
    o0.x = fmaxf(fmaf(acc0.x, inv, bb0.x), 0.f);
    o0.y = fmaxf(fmaf(acc0.y, inv, bb0.y), 0.f);
    o0.z = fmaxf(fmaf(acc0.z, inv, bb0.z), 0.f);
    o0.w = fmaxf(fmaf(acc0.w, inv, bb0.w), 0.f);
    o1.x = fmaxf(fmaf(acc1.x, inv, bb1.x), 0.f);
    o1.y = fmaxf(fmaf(acc1.y, inv, bb1.y), 0.f);
    o1.z = fmaxf(fmaf(acc1.z, inv, bb1.z), 0.f);
    o1.w = fmaxf(fmaf(acc1.w, inv, bb1.w), 0.f);
    float4* mo = (float4*)&g_mha[w * HC];
    mo[f4] = o0;
    mo[f4 + 1] = o1;
}

// Tiled projection (256 -> 64) + residual + LayerNorm + relu, FFMA2 k-pairs.
__global__ void __launch_bounds__(256) k_proj(
    const float* __restrict__ x,
    const float* __restrict__ Wp, const float* __restrict__ bp,
    const float* __restrict__ gam, const float* __restrict__ bet,
    float* __restrict__ out)
{
    __shared__ __align__(8) float xs[32][HC];
    __shared__ __align__(16) float ys[32][CO];
    int tid = threadIdx.x;
    int row0 = blockIdx.x * 32;

    {
        const float4* src = (const float4*)&g_mha[row0 * HC];
        float4* dst = (float4*)&xs[0][0];
#pragma unroll
        for (int i = 0; i < 8; i++) dst[tid + i * 256] = src[tid + i * 256];
    }
    __syncthreads();

    int c = tid & 63;
    int rg = tid >> 6;   // 4 groups of 8 rows
    ull accp[8];
#pragma unroll
    for (int r = 0; r < 8; r++) accp[r] = 0ull;
#pragma unroll 4
    for (int k = 0; k < HC; k += 2) {
        ull wp = pack2(Wp[k * CO + c], Wp[(k + 1) * CO + c]);
#pragma unroll
        for (int r = 0; r < 8; r++) {
            ull a = *(const ull*)&xs[rg * 8 + r][k];   // {xs[r][k], xs[r][k+1]}
            ffma2(accp[r], a, wp);
        }
    }
    float bpc = bp[c];
#pragma unroll
    for (int r = 0; r < 8; r++) {
        int row = rg * 8 + r;
        float2 u = unpack2(accp[r]);
        ys[row][c] = u.x + u.y + bpc + x[(row0 + row) * CC + c];
    }
    __syncthreads();

    int wid = tid >> 5;
    int lane = tid & 31;
    float g0 = gam[lane], g1 = gam[lane + 32];
    float b0 = bet[lane], b1 = bet[lane + 32];
#pragma unroll
    for (int r = 0; r < 4; r++) {
        int row = wid * 4 + r;
        float v0 = ys[row][lane];
        float v1 = ys[row][lane + 32];
        float sv = v0 + v1;
        float sq = v0 * v0 + v1 * v1;
#pragma unroll
        for (int off = 16; off; off >>= 1) {
            sv += __shfl_xor_sync(0xffffffffu, sv, off);
            sq += __shfl_xor_sync(0xffffffffu, sq, off);
        }
        float mu = sv * (1.f / 64.f);
        float var = sq * (1.f / 64.f) - mu * mu;
        float rstd = rsqrtf(var + 1e-5f);
        float y0 = (v0 - mu) * rstd * g0 + b0;
        float y1 = (v1 - mu) * rstd * g1 + b1;
        out[(row0 + row) * CC + lane]      = fmaxf(y0, 0.f);
        out[(row0 + row) * CC + lane + 32] = fmaxf(y1, 0.f);
    }
}

extern "C" void kernel_launch(void* const* d_in, const int* in_sizes, int n_in,
                              void* d_out, int out_size) {
    const float* x    = (const float*)d_in[0];
    const int*   ei   = (const int*)d_in[1];
    const float* Wl   = (const float*)d_in[2];
    const float* bl   = (const float*)d_in[3];
    const float* Wr   = (const float*)d_in[4];
    const float* br   = (const float*)d_in[5];
    const float* att  = (const float*)d_in[6];
    const float* bias = (const float*)d_in[7];
    const float* Wp   = (const float*)d_in[8];
    const float* bp   = (const float*)d_in[9];
    const float* gam  = (const float*)d_in[10];
    const float* bet  = (const float*)d_in[11];
    float* out = (float*)d_out;

    static cudaStream_t s_side = nullptr;
    static cudaEvent_t ev_fork = nullptr, ev_join = nullptr;
    if (!s_side) {
        cudaStreamCreateWithFlags(&s_side, cudaStreamNonBlocking);
        cudaEventCreateWithFlags(&ev_fork, cudaEventDisableTiming);
        cudaEventCreateWithFlags(&ev_join, cudaEventDisableTiming);
    }

    // fork: GEMM (FMA-bound) overlaps the CSR build (atomic/latency-bound)
    cudaEventRecord(ev_fork, 0);
    cudaStreamWaitEvent(s_side, ev_fork, 0);
    k_gemm<<<MROWS / 32, 512, 0, s_side>>>(x, Wl, bl, Wr, br);
    cudaEventRecord(ev_join, s_side);

    k_hist<<<(EE + 255) / 256, 256>>>(ei);
    k_scan<<<1, 1024>>>();
    k_scatter<<<(EE + 255) / 256, 256>>>(ei);

    cudaStreamWaitEvent(0, ev_join, 0);
    k_agg<<<(MROWS + 7) / 8, 256>>>(att, bias);
    k_proj<<<MROWS / 32, 256>>>(x, Wp, bp, gam, bet, out);
}

// round 8
// speedup vs baseline: 1.0642x; 1.0642x over previous
#include <cuda_runtime.h>

#define NN 10000
#define TT 2
#define CC 64
#define HH 4
#define CO 64
#define HC 256
#define EE 160000
#define MROWS (TT*NN)

// scratch (static device allocations; no cudaMalloc allowed)
__device__ float g_xl[MROWS * HC];
__device__ float g_xr[MROWS * HC];
__device__ float g_mha[MROWS * HC];
__device__ int   g_deg[NN];      // zero-initialized; k_scan re-zeroes after use
__device__ int   g_rowptr[NN + 1];
__device__ int   g_cursor[NN];
__device__ int   g_srcs[EE];

// 4 edges per thread via int4
__global__ void k_hist(const int* __restrict__ ei) {
    int i = blockIdx.x * blockDim.x + threadIdx.x;
    if (i < EE / 4) {
        int4 d4 = ((const int4*)(ei + EE))[i];
        atomicAdd(&g_deg[d4.x], 1);
        atomicAdd(&g_deg[d4.y], 1);
        atomicAdd(&g_deg[d4.z], 1);
        atomicAdd(&g_deg[d4.w], 1);
    }
}

__global__ void __launch_bounds__(1024) k_scan() {
    __shared__ int sc[1024];
    int tid = threadIdx.x;
    const int CH = (NN + 1023) / 1024;  // 10
    int base = tid * CH;
    int local = 0;
    for (int j = 0; j < CH; j++) {
        int idx = base + j;
        if (idx < NN) local += g_deg[idx];
    }
    sc[tid] = local;
    __syncthreads();
    for (int off = 1; off < 1024; off <<= 1) {
        int v = (tid >= off) ? sc[tid - off] : 0;
        __syncthreads();
        sc[tid] += v;
        __syncthreads();
    }
    int run = sc[tid] - local;  // exclusive prefix
    for (int j = 0; j < CH; j++) {
        int idx = base + j;
        if (idx < NN) {
            int d = g_deg[idx];
            g_rowptr[idx] = run;
            g_cursor[idx] = run;
            run += d;
            g_deg[idx] = 0;   // reset for next invocation (replay-deterministic)
        }
    }
    if (tid == 1023) g_rowptr[NN] = sc[1023];
}

__global__ void k_scatter(const int* __restrict__ ei) {
    int i = blockIdx.x * blockDim.x + threadIdx.x;
    if (i < EE / 4) {
        int4 s4 = ((const int4*)ei)[i];
        int4 d4 = ((const int4*)(ei + EE))[i];
        g_srcs[atomicAdd(&g_cursor[d4.x], 1)] = s4.x;
        g_srcs[atomicAdd(&g_cursor[d4.y], 1)] = s4.y;
        g_srcs[atomicAdd(&g_cursor[d4.z], 1)] = s4.z;
        g_srcs[atomicAdd(&g_cursor[d4.w], 1)] = s4.w;
    }
}

// Dual GEMM: x_l = x@W_l + b_l,  x_r = x@W_r + b_r.  (proven R4/R6 version)
__global__ void __launch_bounds__(256) k_gemm(
    const float* __restrict__ x,
    const float* __restrict__ Wl, const float* __restrict__ bl,
    const float* __restrict__ Wr, const float* __restrict__ br)
{
    __shared__ float xs[32][64];
    int tid = threadIdx.x;
    int row0 = blockIdx.x * 32;
    for (int i = tid; i < 32 * 64; i += 256) {
        xs[i >> 6][i & 63] = x[(row0 + (i >> 6)) * CC + (i & 63)];
    }
    __syncthreads();
    int c4 = tid & 63;
    int rg = tid >> 6;
    float4 accl[8], accr[8];
#pragma unroll
    for (int r = 0; r < 8; r++) {
        accl[r] = make_float4(0.f, 0.f, 0.f, 0.f);
        accr[r] = make_float4(0.f, 0.f, 0.f, 0.f);
    }
    const float4* Wl4 = (const float4*)Wl;
    const float4* Wr4 = (const float4*)Wr;
#pragma unroll 8
    for (int k = 0; k < 64; k++) {
        float4 wl = Wl4[k * 64 + c4];
        float4 wr = Wr4[k * 64 + c4];
#pragma unroll
        for (int r = 0; r < 8; r++) {
            float xv = xs[rg * 8 + r][k];
            accl[r].x = fmaf(xv, wl.x, accl[r].x);
            accl[r].y = fmaf(xv, wl.y, accl[r].y);
            accl[r].z = fmaf(xv, wl.z, accl[r].z);
            accl[r].w = fmaf(xv, wl.w, accl[r].w);
            accr[r].x = fmaf(xv, wr.x, accr[r].x);
            accr[r].y = fmaf(xv, wr.y, accr[r].y);
            accr[r].z = fmaf(xv, wr.z, accr[r].z);
            accr[r].w = fmaf(xv, wr.w, accr[r].w);
        }
    }
    float4 bl4 = ((const float4*)bl)[c4];
    float4 br4 = ((const float4*)br)[c4];
#pragma unroll
    for (int r = 0; r < 8; r++) {
        int row = row0 + rg * 8 + r;
        float4 ol, orr;
        ol.x = accl[r].x + bl4.x; ol.y = accl[r].y + bl4.y;
        ol.z = accl[r].z + bl4.z; ol.w = accl[r].w + bl4.w;
        orr.x = accr[r].x + br4.x; orr.y = accr[r].y + br4.y;
        orr.z = accr[r].z + br4.z; orr.w = accr[r].w + br4.w;
        ((float4*)g_xl)[row * 64 + c4] = ol;
        ((float4*)g_xr)[row * 64 + c4] = orr;
    }
}

// GAT aggregation: one WARP per (t, n). Single pass, no-max softmax.
// Lane L owns head (L>>3), dims [(L&7)*8, +8) -> float4 indices 2L, 2L+1.
// 3-deep software pipeline (6 outstanding LDG.128/warp).
__device__ __forceinline__ int get_src(int k, int s0, int s1, int base) {
    if (k < 32) return __shfl_sync(0xffffffffu, s0, k);
    if (k < 64) return __shfl_sync(0xffffffffu, s1, k - 32);
    return g_srcs[base + k];
}

__global__ void __launch_bounds__(256) k_agg(
    const float* __restrict__ att,
    const float* __restrict__ bias)
{
    int w = blockIdx.x * 8 + (threadIdx.x >> 5);
    if (w >= MROWS) return;
    int lane = threadIdx.x & 31;
    int n = w % NN;
    int t = w / NN;
    int f4 = lane * 2;

    const float4* xr = (const float4*)&g_xr[w * HC];
    float4 xr0 = xr[f4];
    float4 xr1 = xr[f4 + 1];
    float4 at0 = ((const float4*)att)[f4];
    float4 at1 = ((const float4*)att)[f4 + 1];

    int base = g_rowptr[n];
    int deg = g_rowptr[n + 1] - base;

    int s0 = (lane < deg) ? g_srcs[base + lane] : 0;
    int s1 = (32 + lane < deg) ? g_srcs[base + 32 + lane] : 0;

    float den = 0.f;
    float4 acc0 = make_float4(0.f, 0.f, 0.f, 0.f);
    float4 acc1 = make_float4(0.f, 0.f, 0.f, 0.f);
    int xlbase = t * NN * HC;

    float4 A0, A1, B0, B1, C0, C1;
    if (deg > 0) {
        const float4* xl = (const float4*)&g_xl[xlbase + get_src(0, s0, s1, base) * HC];
        A0 = xl[f4]; A1 = xl[f4 + 1];
    }
    if (deg > 1) {
        const float4* xl = (const float4*)&g_xl[xlbase + get_src(1, s0, s1, base) * HC];
        B0 = xl[f4]; B1 = xl[f4 + 1];
    }
    if (deg > 2) {
        const float4* xl = (const float4*)&g_xl[xlbase + get_src(2, s0, s1, base) * HC];
        C0 = xl[f4]; C1 = xl[f4 + 1];
    }

#define AGG_BODY(a0, a1)                                                     \
    {                                                                        \
        float v, p;                                                          \
        v = a0.x + xr0.x; v = fmaxf(v, 0.2f * v); p = v * at0.x;             \
        v = a0.y + xr0.y; v = fmaxf(v, 0.2f * v); p = fmaf(v, at0.y, p);     \
        v = a0.z + xr0.z; v = fmaxf(v, 0.2f * v); p = fmaf(v, at0.z, p);     \
        v = a0.w + xr0.w; v = fmaxf(v, 0.2f * v); p = fmaf(v, at0.w, p);     \
        v = a1.x + xr1.x; v = fmaxf(v, 0.2f * v); p = fmaf(v, at1.x, p);     \
        v = a1.y + xr1.y; v = fmaxf(v, 0.2f * v); p = fmaf(v, at1.y, p);     \
        v = a1.z + xr1.z; v = fmaxf(v, 0.2f * v); p = fmaf(v, at1.z, p);     \
        v = a1.w + xr1.w; v = fmaxf(v, 0.2f * v); p = fmaf(v, at1.w, p);     \
        p += __shfl_xor_sync(0xffffffffu, p, 1);                             \
        p += __shfl_xor_sync(0xffffffffu, p, 2);                             \
        p += __shfl_xor_sync(0xffffffffu, p, 4);                             \
        float e = __expf(p);                                                 \
        den += e;                                                            \
        acc0.x = fmaf(e, a0.x, acc0.x);                                      \
        acc0.y = fmaf(e, a0.y, acc0.y);                                      \
        acc0.z = fmaf(e, a0.z, acc0.z);                                      \
        acc0.w = fmaf(e, a0.w, acc0.w);                                      \
        acc1.x = fmaf(e, a1.x, acc1.x);                                      \
        acc1.y = fmaf(e, a1.y, acc1.y);                                      \
        acc1.z = fmaf(e, a1.z, acc1.z);                                      \
        acc1.w = fmaf(e, a1.w, acc1.w);                                      \
    }

#define AGG_STEP(R0, R1)                                                     \
    {                                                                        \
        float4 a0 = R0, a1 = R1;                                             \
        if (k + 3 < deg) {                                                   \
            const float4* xl =                                               \
                (const float4*)&g_xl[xlbase + get_src(k + 3, s0, s1, base) * HC]; \
            R0 = xl[f4]; R1 = xl[f4 + 1];                                    \
        }                                                                    \
        AGG_BODY(a0, a1);                                                    \
        k++;                                                                 \
    }

    int k = 0;
    while (k < deg) {
        AGG_STEP(A0, A1);
        if (k >= deg) break;
        AGG_STEP(B0, B1);
        if (k >= deg) break;
        AGG_STEP(C0, C1);
    }
#undef AGG_STEP
#undef AGG_BODY

    float inv = (deg > 0) ? 1.0f / den : 0.f;
    const float4* b4 = (const float4*)bias;
    float4 bb0 = b4[f4], bb1 = b4[f4 + 1];
    float4 o0, o1;
    o0.x = fmaxf(fmaf(acc0.x, inv, bb0.x), 0.f);
    o0.y = fmaxf(fmaf(acc0.y, inv, bb0.y), 0.f);
    o0.z = fmaxf(fmaf(acc0.z, inv, bb0.z), 0.f);
    o0.w = fmaxf(fmaf(acc0.w, inv, bb0.w), 0.f);
    o1.x = fmaxf(fmaf(acc1.x, inv, bb1.x), 0.f);
    o1.y = fmaxf(fmaf(acc1.y, inv, bb1.y), 0.f);
    o1.z = fmaxf(fmaf(acc1.z, inv, bb1.z), 0.f);
    o1.w = fmaxf(fmaf(acc1.w, inv, bb1.w), 0.f);
    float4* mo = (float4*)&g_mha[w * HC];
    mo[f4] = o0;
    mo[f4 + 1] = o1;
}

// Tiled projection (256 -> 64) + residual + LayerNorm + relu.  (R6 version)
__global__ void __launch_bounds__(256) k_proj(
    const float* __restrict__ x,
    const float* __restrict__ Wp, const float* __restrict__ bp,
    const float* __restrict__ gam, const float* __restrict__ bet,
    float* __restrict__ out)
{
    __shared__ __align__(16) float xs[32][HC];
    __shared__ __align__(16) float ys[32][CO];
    int tid = threadIdx.x;
    int row0 = blockIdx.x * 32;

    {
        const float4* src = (const float4*)&g_mha[row0 * HC];
        float4* dst = (float4*)&xs[0][0];
#pragma unroll
        for (int i = 0; i < 8; i++) dst[tid + i * 256] = src[tid + i * 256];
    }
    __syncthreads();

    int c = tid & 63;
    int rg = tid >> 6;
    float acc[8];
#pragma unroll
    for (int r = 0; r < 8; r++) acc[r] = 0.f;
#pragma unroll 4
    for (int k = 0; k < HC; k++) {
        float w = Wp[k * CO + c];
#pragma unroll
        for (int r = 0; r < 8; r++) {
            acc[r] = fmaf(xs[rg * 8 + r][k], w, acc[r]);
        }
    }
    float bpc = bp[c];
#pragma unroll
    for (int r = 0; r < 8; r++) {
        int row = rg * 8 + r;
        ys[row][c] = acc[r] + bpc + x[(row0 + row) * CC + c];
    }
    __syncthreads();

    int wid = tid >> 5;
    int lane = tid & 31;
    float g0 = gam[lane], g1 = gam[lane + 32];
    float b0 = bet[lane], b1 = bet[lane + 32];
#pragma unroll
    for (int r = 0; r < 4; r++) {
        int row = wid * 4 + r;
        float v0 = ys[row][lane];
        float v1 = ys[row][lane + 32];
        float sv = v0 + v1;
        float sq = v0 * v0 + v1 * v1;
#pragma unroll
        for (int off = 16; off; off >>= 1) {
            sv += __shfl_xor_sync(0xffffffffu, sv, off);
            sq += __shfl_xor_sync(0xffffffffu, sq, off);
        }
        float mu = sv * (1.f / 64.f);
        float var = sq * (1.f / 64.f) - mu * mu;
        float rstd = rsqrtf(var + 1e-5f);
        float y0 = (v0 - mu) * rstd * g0 + b0;
        float y1 = (v1 - mu) * rstd * g1 + b1;
        out[(row0 + row) * CC + lane]      = fmaxf(y0, 0.f);
        out[(row0 + row) * CC + lane + 32] = fmaxf(y1, 0.f);
    }
}

extern "C" void kernel_launch(void* const* d_in, const int* in_sizes, int n_in,
                              void* d_out, int out_size) {
    const float* x    = (const float*)d_in[0];
    const int*   ei   = (const int*)d_in[1];
    const float* Wl   = (const float*)d_in[2];
    const float* bl   = (const float*)d_in[3];
    const float* Wr   = (const float*)d_in[4];
    const float* br   = (const float*)d_in[5];
    const float* att  = (const float*)d_in[6];
    const float* bias = (const float*)d_in[7];
    const float* Wp   = (const float*)d_in[8];
    const float* bp   = (const float*)d_in[9];
    const float* gam  = (const float*)d_in[10];
    const float* bet  = (const float*)d_in[11];
    float* out = (float*)d_out;

    static cudaStream_t s_side = nullptr;
    static cudaEvent_t ev_fork = nullptr, ev_join = nullptr;
    if (!s_side) {
        cudaStreamCreateWithFlags(&s_side, cudaStreamNonBlocking);
        cudaEventCreateWithFlags(&ev_fork, cudaEventDisableTiming);
        cudaEventCreateWithFlags(&ev_join, cudaEventDisableTiming);
    }

    // fork: GEMM (FMA-bound) overlaps the CSR build (atomic/latency-bound)
    cudaEventRecord(ev_fork, 0);
    cudaStreamWaitEvent(s_side, ev_fork, 0);
    k_gemm<<<MROWS / 32, 256, 0, s_side>>>(x, Wl, bl, Wr, br);
    cudaEventRecord(ev_join, s_side);

    k_hist<<<(EE / 4 + 255) / 256, 256>>>(ei);
    k_scan<<<1, 1024>>>();
    k_scatter<<<(EE / 4 + 255) / 256, 256>>>(ei);

    cudaStreamWaitEvent(0, ev_join, 0);
    k_agg<<<(MROWS + 7) / 8, 256>>>(att, bias);
    k_proj<<<MROWS / 32, 256>>>(x, Wp, bp, gam, bet, out);
}

// round 9
// speedup vs baseline: 1.1244x; 1.0565x over previous
#include <cuda_runtime.h>
#include <cuda_fp16.h>

#define NN 10000
#define TT 2
#define CC 64
#define HH 4
#define CO 64
#define HC 256
#define EE 160000
#define MROWS (TT*NN)

// scratch (static device allocations; no cudaMalloc allowed)
__device__ __half g_xlh[MROWS * HC];   // x_l in fp16 (gathered tensor)
__device__ float  g_xr[MROWS * HC];
__device__ float  g_mha[MROWS * HC];
__device__ int    g_deg[NN];           // zero-initialized; k_scan re-zeroes after use
__device__ int    g_rowptr[NN + 1];
__device__ int    g_cursor[NN];
__device__ int    g_srcs[EE];

// 4 edges per thread via int4
__global__ void k_hist(const int* __restrict__ ei) {
    int i = blockIdx.x * blockDim.x + threadIdx.x;
    if (i < EE / 4) {
        int4 d4 = ((const int4*)(ei + EE))[i];
        atomicAdd(&g_deg[d4.x], 1);
        atomicAdd(&g_deg[d4.y], 1);
        atomicAdd(&g_deg[d4.z], 1);
        atomicAdd(&g_deg[d4.w], 1);
    }
}

__global__ void __launch_bounds__(1024) k_scan() {
    __shared__ int sc[1024];
    int tid = threadIdx.x;
    const int CH = (NN + 1023) / 1024;  // 10
    int base = tid * CH;
    int local = 0;
    for (int j = 0; j < CH; j++) {
        int idx = base + j;
        if (idx < NN) local += g_deg[idx];
    }
    sc[tid] = local;
    __syncthreads();
    for (int off = 1; off < 1024; off <<= 1) {
        int v = (tid >= off) ? sc[tid - off] : 0;
        __syncthreads();
        sc[tid] += v;
        __syncthreads();
    }
    int run = sc[tid] - local;  // exclusive prefix
    for (int j = 0; j < CH; j++) {
        int idx = base + j;
        if (idx < NN) {
            int d = g_deg[idx];
            g_rowptr[idx] = run;
            g_cursor[idx] = run;
            run += d;
            g_deg[idx] = 0;   // reset for next invocation (replay-deterministic)
        }
    }
    if (tid == 1023) g_rowptr[NN] = sc[1023];
}

__global__ void k_scatter(const int* __restrict__ ei) {
    int i = blockIdx.x * blockDim.x + threadIdx.x;
    if (i < EE / 4) {
        int4 s4 = ((const int4*)ei)[i];
        int4 d4 = ((const int4*)(ei + EE))[i];
        g_srcs[atomicAdd(&g_cursor[d4.x], 1)] = s4.x;
        g_srcs[atomicAdd(&g_cursor[d4.y], 1)] = s4.y;
        g_srcs[atomicAdd(&g_cursor[d4.z], 1)] = s4.z;
        g_srcs[atomicAdd(&g_cursor[d4.w], 1)] = s4.w;
    }
}

// Dual GEMM: x_l = x@W_l + b_l (stored fp16),  x_r = x@W_r + b_r (fp32).
__global__ void __launch_bounds__(256) k_gemm(
    const float* __restrict__ x,
    const float* __restrict__ Wl, const float* __restrict__ bl,
    const float* __restrict__ Wr, const float* __restrict__ br)
{
    __shared__ float xs[32][64];
    int tid = threadIdx.x;
    int row0 = blockIdx.x * 32;
    for (int i = tid; i < 32 * 64; i += 256) {
        xs[i >> 6][i & 63] = x[(row0 + (i >> 6)) * CC + (i & 63)];
    }
    __syncthreads();
    int c4 = tid & 63;
    int rg = tid >> 6;
    float4 accl[8], accr[8];
#pragma unroll
    for (int r = 0; r < 8; r++) {
        accl[r] = make_float4(0.f, 0.f, 0.f, 0.f);
        accr[r] = make_float4(0.f, 0.f, 0.f, 0.f);
    }
    const float4* Wl4 = (const float4*)Wl;
    const float4* Wr4 = (const float4*)Wr;
#pragma unroll 8
    for (int k = 0; k < 64; k++) {
        float4 wl = Wl4[k * 64 + c4];
        float4 wr = Wr4[k * 64 + c4];
#pragma unroll
        for (int r = 0; r < 8; r++) {
            float xv = xs[rg * 8 + r][k];
            accl[r].x = fmaf(xv, wl.x, accl[r].x);
            accl[r].y = fmaf(xv, wl.y, accl[r].y);
            accl[r].z = fmaf(xv, wl.z, accl[r].z);
            accl[r].w = fmaf(xv, wl.w, accl[r].w);
            accr[r].x = fmaf(xv, wr.x, accr[r].x);
            accr[r].y = fmaf(xv, wr.y, accr[r].y);
            accr[r].z = fmaf(xv, wr.z, accr[r].z);
            accr[r].w = fmaf(xv, wr.w, accr[r].w);
        }
    }
    float4 bl4 = ((const float4*)bl)[c4];
    float4 br4 = ((const float4*)br)[c4];
#pragma unroll
    for (int r = 0; r < 8; r++) {
        int row = row0 + rg * 8 + r;
        float ox = accl[r].x + bl4.x, oy = accl[r].y + bl4.y;
        float oz = accl[r].z + bl4.z, ow = accl[r].w + bl4.w;
        // fp16 store: 2x half2 = 8 bytes at row*256 + c4*4
        __half2 p0 = __floats2half2_rn(ox, oy);
        __half2 p1 = __floats2half2_rn(oz, ow);
        uint2 pk;
        pk.x = *(unsigned*)&p0;
        pk.y = *(unsigned*)&p1;
        ((uint2*)g_xlh)[row * 64 + c4] = pk;
        float4 orr;
        orr.x = accr[r].x + br4.x; orr.y = accr[r].y + br4.y;
        orr.z = accr[r].z + br4.z; orr.w = accr[r].w + br4.w;
        ((float4*)g_xr)[row * 64 + c4] = orr;
    }
}

// GAT aggregation: one WARP per (t, n). Single pass, no-max softmax.
// Lane L owns head (L>>3), dims [(L&7)*8, +8).
// x_l gathered as fp16: one uint4 (8 halves = 16B) per lane per edge.
// 4-deep software pipeline (4 outstanding LDG.128/warp).
__device__ __forceinline__ int get_src(int k, int s0, int s1, int base) {
    if (k < 32) return __shfl_sync(0xffffffffu, s0, k);
    if (k < 64) return __shfl_sync(0xffffffffu, s1, k - 32);
    return g_srcs[base + k];
}

__device__ __forceinline__ void h2f8(uint4 u, float4& a0, float4& a1) {
    float2 f0 = __half22float2(*(__half2*)&u.x);
    float2 f1 = __half22float2(*(__half2*)&u.y);
    float2 f2 = __half22float2(*(__half2*)&u.z);
    float2 f3 = __half22float2(*(__half2*)&u.w);
    a0 = make_float4(f0.x, f0.y, f1.x, f1.y);
    a1 = make_float4(f2.x, f2.y, f3.x, f3.y);
}

__global__ void __launch_bounds__(256) k_agg(
    const float* __restrict__ att,
    const float* __restrict__ bias)
{
    int w = blockIdx.x * 8 + (threadIdx.x >> 5);
    if (w >= MROWS) return;
    int lane = threadIdx.x & 31;
    int n = w % NN;
    int t = w / NN;
    int f4 = lane * 2;

    const float4* xr = (const float4*)&g_xr[w * HC];
    float4 xr0 = xr[f4];
    float4 xr1 = xr[f4 + 1];
    float4 at0 = ((const float4*)att)[f4];
    float4 at1 = ((const float4*)att)[f4 + 1];

    int base = g_rowptr[n];
    int deg = g_rowptr[n + 1] - base;

    int s0 = (lane < deg) ? g_srcs[base + lane] : 0;
    int s1 = (32 + lane < deg) ? g_srcs[base + 32 + lane] : 0;

    float den = 0.f;
    float4 acc0 = make_float4(0.f, 0.f, 0.f, 0.f);
    float4 acc1 = make_float4(0.f, 0.f, 0.f, 0.f);
    // lane's uint4 index within a row: row*(HC/8) + lane  (16B per lane)
    const uint4* xlh4 = (const uint4*)g_xlh;
    int xlbase = t * NN * (HC / 8);

    uint4 A, B, C, D;
    if (deg > 0) A = xlh4[xlbase + get_src(0, s0, s1, base) * (HC / 8) + lane];
    if (deg > 1) B = xlh4[xlbase + get_src(1, s0, s1, base) * (HC / 8) + lane];
    if (deg > 2) C = xlh4[xlbase + get_src(2, s0, s1, base) * (HC / 8) + lane];
    if (deg > 3) D = xlh4[xlbase + get_src(3, s0, s1, base) * (HC / 8) + lane];

#define AGG_BODY(u)                                                          \
    {                                                                        \
        float4 a0, a1;                                                       \
        h2f8(u, a0, a1);                                                     \
        float v, p;                                                          \
        v = a0.x + xr0.x; v = fmaxf(v, 0.2f * v); p = v * at0.x;             \
        v = a0.y + xr0.y; v = fmaxf(v, 0.2f * v); p = fmaf(v, at0.y, p);     \
        v = a0.z + xr0.z; v = fmaxf(v, 0.2f * v); p = fmaf(v, at0.z, p);     \
        v = a0.w + xr0.w; v = fmaxf(v, 0.2f * v); p = fmaf(v, at0.w, p);     \
        v = a1.x + xr1.x; v = fmaxf(v, 0.2f * v); p = fmaf(v, at1.x, p);     \
        v = a1.y + xr1.y; v = fmaxf(v, 0.2f * v); p = fmaf(v, at1.y, p);     \
        v = a1.z + xr1.z; v = fmaxf(v, 0.2f * v); p = fmaf(v, at1.z, p);     \
        v = a1.w + xr1.w; v = fmaxf(v, 0.2f * v); p = fmaf(v, at1.w, p);     \
        p += __shfl_xor_sync(0xffffffffu, p, 1);                             \
        p += __shfl_xor_sync(0xffffffffu, p, 2);                             \
        p += __shfl_xor_sync(0xffffffffu, p, 4);                             \
        float e = __expf(p);                                                 \
        den += e;                                                            \
        acc0.x = fmaf(e, a0.x, acc0.x);                                      \
        acc0.y = fmaf(e, a0.y, acc0.y);                                      \
        acc0.z = fmaf(e, a0.z, acc0.z);                                      \
        acc0.w = fmaf(e, a0.w, acc0.w);                                      \
        acc1.x = fmaf(e, a1.x, acc1.x);                                      \
        acc1.y = fmaf(e, a1.y, acc1.y);                                      \
        acc1.z = fmaf(e, a1.z, acc1.z);                                      \
        acc1.w = fmaf(e, a1.w, acc1.w);                                      \
    }

#define AGG_STEP(R)                                                          \
    {                                                                        \
        uint4 u = R;                                                         \
        if (k + 4 < deg)                                                     \
            R = xlh4[xlbase + get_src(k + 4, s0, s1, base) * (HC / 8) + lane]; \
        AGG_BODY(u);                                                         \
        k++;                                                                 \
    }

    int k = 0;
    while (k < deg) {
        AGG_STEP(A);
        if (k >= deg) break;
        AGG_STEP(B);
        if (k >= deg) break;
        AGG_STEP(C);
        if (k >= deg) break;
        AGG_STEP(D);
    }
#undef AGG_STEP
#undef AGG_BODY

    float inv = (deg > 0) ? 1.0f / den : 0.f;
    const float4* b4 = (const float4*)bias;
    float4 bb0 = b4[f4], bb1 = b4[f4 + 1];
    float4 o0, o1;
    o0.x = fmaxf(fmaf(acc0.x, inv, bb0.x), 0.f);
    o0.y = fmaxf(fmaf(acc0.y, inv, bb0.y), 0.f);
    o0.z = fmaxf(fmaf(acc0.z, inv, bb0.z), 0.f);
    o0.w = fmaxf(fmaf(acc0.w, inv, bb0.w), 0.f);
    o1.x = fmaxf(fmaf(acc1.x, inv, bb1.x), 0.f);
    o1.y = fmaxf(fmaf(acc1.y, inv, bb1.y), 0.f);
    o1.z = fmaxf(fmaf(acc1.z, inv, bb1.z), 0.f);
    o1.w = fmaxf(fmaf(acc1.w, inv, bb1.w), 0.f);
    float4* mo = (float4*)&g_mha[w * HC];
    mo[f4] = o0;
    mo[f4 + 1] = o1;
}

// Tiled projection (256 -> 64) + residual + LayerNorm + relu.
__global__ void __launch_bounds__(256) k_proj(
    const float* __restrict__ x,
    const float* __restrict__ Wp, const float* __restrict__ bp,
    const float* __restrict__ gam, const float* __restrict__ bet,
    float* __restrict__ out)
{
    __shared__ __align__(16) float xs[32][HC];
    __shared__ __align__(16) float ys[32][CO];
    int tid = threadIdx.x;
    int row0 = blockIdx.x * 32;

    {
        const float4* src = (const float4*)&g_mha[row0 * HC];
        float4* dst = (float4*)&xs[0][0];
#pragma unroll
        for (int i = 0; i < 8; i++) dst[tid + i * 256] = src[tid + i * 256];
    }
    __syncthreads();

    int c = tid & 63;
    int rg = tid >> 6;
    float acc[8];
#pragma unroll
    for (int r = 0; r < 8; r++) acc[r] = 0.f;
#pragma unroll 4
    for (int k = 0; k < HC; k++) {
        float w = Wp[k * CO + c];
#pragma unroll
        for (int r = 0; r < 8; r++) {
            acc[r] = fmaf(xs[rg * 8 + r][k], w, acc[r]);
        }
    }
    float bpc = bp[c];
#pragma unroll
    for (int r = 0; r < 8; r++) {
        int row = rg * 8 + r;
        ys[row][c] = acc[r] + bpc + x[(row0 + row) * CC + c];
    }
    __syncthreads();

    int wid = tid >> 5;
    int lane = tid & 31;
    float g0 = gam[lane], g1 = gam[lane + 32];
    float b0 = bet[lane], b1 = bet[lane + 32];
#pragma unroll
    for (int r = 0; r < 4; r++) {
        int row = wid * 4 + r;
        float v0 = ys[row][lane];
        float v1 = ys[row][lane + 32];
        float sv = v0 + v1;
        float sq = v0 * v0 + v1 * v1;
#pragma unroll
        for (int off = 16; off; off >>= 1) {
            sv += __shfl_xor_sync(0xffffffffu, sv, off);
            sq += __shfl_xor_sync(0xffffffffu, sq, off);
        }
        float mu = sv * (1.f / 64.f);
        float var = sq * (1.f / 64.f) - mu * mu;
        float rstd = rsqrtf(var + 1e-5f);
        float y0 = (v0 - mu) * rstd * g0 + b0;
        float y1 = (v1 - mu) * rstd * g1 + b1;
        out[(row0 + row) * CC + lane]      = fmaxf(y0, 0.f);
        out[(row0 + row) * CC + lane + 32] = fmaxf(y1, 0.f);
    }
}

extern "C" void kernel_launch(void* const* d_in, const int* in_sizes, int n_in,
                              void* d_out, int out_size) {
    const float* x    = (const float*)d_in[0];
    const int*   ei   = (const int*)d_in[1];
    const float* Wl   = (const float*)d_in[2];
    const float* bl   = (const float*)d_in[3];
    const float* Wr   = (const float*)d_in[4];
    const float* br   = (const float*)d_in[5];
    const float* att  = (const float*)d_in[6];
    const float* bias = (const float*)d_in[7];
    const float* Wp   = (const float*)d_in[8];
    const float* bp   = (const float*)d_in[9];
    const float* gam  = (const float*)d_in[10];
    const float* bet  = (const float*)d_in[11];
    float* out = (float*)d_out;

    static cudaStream_t s_side = nullptr;
    static cudaEvent_t ev_fork = nullptr, ev_join = nullptr;
    if (!s_side) {
        cudaStreamCreateWithFlags(&s_side, cudaStreamNonBlocking);
        cudaEventCreateWithFlags(&ev_fork, cudaEventDisableTiming);
        cudaEventCreateWithFlags(&ev_join, cudaEventDisableTiming);
    }

    // fork: GEMM (FMA-bound) overlaps the CSR build (atomic/latency-bound)
    cudaEventRecord(ev_fork, 0);
    cudaStreamWaitEvent(s_side, ev_fork, 0);
    k_gemm<<<MROWS / 32, 256, 0, s_side>>>(x, Wl, bl, Wr, br);
    cudaEventRecord(ev_join, s_side);

    k_hist<<<(EE / 4 + 255) / 256, 256>>>(ei);
    k_scan<<<1, 1024>>>();
    k_scatter<<<(EE / 4 + 255) / 256, 256>>>(ei);

    cudaStreamWaitEvent(0, ev_join, 0);
    k_agg<<<(MROWS + 7) / 8, 256>>>(att, bias);
    k_proj<<<MROWS / 32, 256>>>(x, Wp, bp, gam, bet, out);
}

// round 10
// speedup vs baseline: 1.2487x; 1.1106x over previous
#include <cuda_runtime.h>
#include <cuda_fp16.h>

#define NN 10000
#define TT 2
#define CC 64
#define HH 4
#define CO 64
#define HC 256
#define EE 160000
#define MROWS (TT*NN)

// scratch (static device allocations; no cudaMalloc allowed)
__device__ __half g_xlh[MROWS * HC];   // x_l in fp16 (gathered tensor)
__device__ float  g_xr[MROWS * HC];
__device__ float  g_mha[MROWS * HC];
__device__ int    g_deg[NN];           // zero-initialized; k_scan re-zeroes after use
__device__ int    g_rowptr[NN + 1];
__device__ int    g_cursor[NN];
__device__ int    g_srcs[EE];

// 4 edges per thread via int4
__global__ void k_hist(const int* __restrict__ ei) {
    int i = blockIdx.x * blockDim.x + threadIdx.x;
    if (i < EE / 4) {
        int4 d4 = ((const int4*)(ei + EE))[i];
        atomicAdd(&g_deg[d4.x], 1);
        atomicAdd(&g_deg[d4.y], 1);
        atomicAdd(&g_deg[d4.z], 1);
        atomicAdd(&g_deg[d4.w], 1);
    }
}

__global__ void __launch_bounds__(1024) k_scan() {
    __shared__ int sc[1024];
    int tid = threadIdx.x;
    const int CH = (NN + 1023) / 1024;  // 10
    int base = tid * CH;
    int local = 0;
    for (int j = 0; j < CH; j++) {
        int idx = base + j;
        if (idx < NN) local += g_deg[idx];
    }
    sc[tid] = local;
    __syncthreads();
    for (int off = 1; off < 1024; off <<= 1) {
        int v = (tid >= off) ? sc[tid - off] : 0;
        __syncthreads();
        sc[tid] += v;
        __syncthreads();
    }
    int run = sc[tid] - local;  // exclusive prefix
    for (int j = 0; j < CH; j++) {
        int idx = base + j;
        if (idx < NN) {
            int d = g_deg[idx];
            g_rowptr[idx] = run;
            g_cursor[idx] = run;
            run += d;
            g_deg[idx] = 0;   // reset for next invocation (replay-deterministic)
        }
    }
    if (tid == 1023) g_rowptr[NN] = sc[1023];
}

__global__ void k_scatter(const int* __restrict__ ei) {
    int i = blockIdx.x * blockDim.x + threadIdx.x;
    if (i < EE / 4) {
        int4 s4 = ((const int4*)ei)[i];
        int4 d4 = ((const int4*)(ei + EE))[i];
        g_srcs[atomicAdd(&g_cursor[d4.x], 1)] = s4.x;
        g_srcs[atomicAdd(&g_cursor[d4.y], 1)] = s4.y;
        g_srcs[atomicAdd(&g_cursor[d4.z], 1)] = s4.z;
        g_srcs[atomicAdd(&g_cursor[d4.w], 1)] = s4.w;
    }
}

// ================= Tensor-core dual GEMM =================
// [x_l | x_r](row, 0..511) = x(row, :) @ [W_l | W_r] + [b_l | b_r]
// mma.m16n8k16 f16xf16->f32. Block: 256 thr = 8 warps, 128 rows.
// smem: xs [128][72] half (fp16 x tile), Wt [512][72] half (W^T, n-major).
// 72-half row stride => bank = 4*(lane>>2) + (lane&3): conflict-free LDS.32.
#define XS_STRIDE 72
#define GEMM_SMEM ((128 * XS_STRIDE + 512 * XS_STRIDE) * 2)

__device__ __forceinline__ unsigned ldsm(const __half* p) {
    return *(const unsigned*)p;
}

__device__ __forceinline__ void mma16816(float* d, const unsigned* a,
                                         unsigned b0, unsigned b1) {
    asm volatile(
        "mma.sync.aligned.m16n8k16.row.col.f32.f16.f16.f32 "
        "{%0,%1,%2,%3}, {%4,%5,%6,%7}, {%8,%9}, {%0,%1,%2,%3};\n"
        : "+f"(d[0]), "+f"(d[1]), "+f"(d[2]), "+f"(d[3])
        : "r"(a[0]), "r"(a[1]), "r"(a[2]), "r"(a[3]), "r"(b0), "r"(b1));
}

__global__ void __launch_bounds__(256) k_gemm(
    const float* __restrict__ x,
    const float* __restrict__ Wl, const float* __restrict__ bl,
    const float* __restrict__ Wr, const float* __restrict__ br)
{
    extern __shared__ __half smem[];
    __half* xs = smem;                       // [128][72]
    __half* Wt = smem + 128 * XS_STRIDE;     // [512][72]

    int tid = threadIdx.x;
    int row0 = blockIdx.x * 128;

    // load x tile (fp32 -> fp16), coalesced
#pragma unroll
    for (int it = 0; it < 32; it++) {
        int flat = it * 256 + tid;           // 128*64
        int r = flat >> 6, c = flat & 63;
        int grow = row0 + r;
        float v = (grow < MROWS) ? x[grow * CC + c] : 0.f;
        xs[r * XS_STRIDE + c] = __float2half(v);
    }
    // load W^T: Wt[n][k] = W[k][n], coalesced over n
#pragma unroll
    for (int it = 0; it < 128; it++) {
        int flat = it * 256 + tid;           // 64*512
        int k = flat >> 9, n = flat & 511;
        float v = (n < HC) ? Wl[k * HC + n] : Wr[k * HC + (n - HC)];
        Wt[n * XS_STRIDE + k] = __float2half(v);
    }
    __syncthreads();

    int lane = tid & 31;
    int wid = tid >> 5;
    int g = lane >> 2;       // group 0..7
    int q = lane & 3;        // quad 0..3
    int wm = wid * 16;       // warp row base in tile

    // preload all A fragments (4 k-steps x 4 regs)
    unsigned Areg[4][4];
#pragma unroll
    for (int ks = 0; ks < 4; ks++) {
        int kb = ks * 16 + q * 2;
        Areg[ks][0] = ldsm(&xs[(wm + g) * XS_STRIDE + kb]);
        Areg[ks][1] = ldsm(&xs[(wm + g + 8) * XS_STRIDE + kb]);
        Areg[ks][2] = ldsm(&xs[(wm + g) * XS_STRIDE + kb + 8]);
        Areg[ks][3] = ldsm(&xs[(wm + g + 8) * XS_STRIDE + kb + 8]);
    }

    int row_lo = row0 + wm + g;
    int row_hi = row_lo + 8;

#pragma unroll 1
    for (int chunk = 0; chunk < 8; chunk++) {
        float d[8][4];
#pragma unroll
        for (int nt = 0; nt < 8; nt++)
#pragma unroll
            for (int e = 0; e < 4; e++) d[nt][e] = 0.f;

#pragma unroll
        for (int ks = 0; ks < 4; ks++) {
            int kb = ks * 16 + q * 2;
#pragma unroll
            for (int nt = 0; nt < 8; nt++) {
                int n = chunk * 64 + nt * 8 + g;
                unsigned b0 = ldsm(&Wt[n * XS_STRIDE + kb]);
                unsigned b1 = ldsm(&Wt[n * XS_STRIDE + kb + 8]);
                mma16816(d[nt], Areg[ks], b0, b1);
            }
        }

        // epilogue: bias + store (x_l fp16 for chunks 0-3, x_r fp32 for 4-7)
#pragma unroll
        for (int nt = 0; nt < 8; nt++) {
            int colg = chunk * 64 + nt * 8 + q * 2;   // 0..511
            if (colg < HC) {
                float b0v = bl[colg], b1v = bl[colg + 1];
                if (row_lo < MROWS) {
                    __half2 h = __floats2half2_rn(d[nt][0] + b0v, d[nt][1] + b1v);
                    *(__half2*)&g_xlh[row_lo * HC + colg] = h;
                }
                if (row_hi < MROWS) {
                    __half2 h = __floats2half2_rn(d[nt][2] + b0v, d[nt][3] + b1v);
                    *(__half2*)&g_xlh[row_hi * HC + colg] = h;
                }
            } else {
                int c = colg - HC;
                float b0v = br[c], b1v = br[c + 1];
                if (row_lo < MROWS) {
                    float2 f = make_float2(d[nt][0] + b0v, d[nt][1] + b1v);
                    *(float2*)&g_xr[row_lo * HC + c] = f;
                }
                if (row_hi < MROWS) {
                    float2 f = make_float2(d[nt][2] + b0v, d[nt][3] + b1v);
                    *(float2*)&g_xr[row_hi * HC + c] = f;
                }
            }
        }
    }
}

// GAT aggregation: one WARP per (t, n). Single pass, no-max softmax.
// Lane L owns head (L>>3), dims [(L&7)*8, +8).
// x_l gathered as fp16: one uint4 (8 halves = 16B) per lane per edge.
// 4-deep software pipeline.
__device__ __forceinline__ int get_src(int k, int s0, int s1, int base) {
    if (k < 32) return __shfl_sync(0xffffffffu, s0, k);
    if (k < 64) return __shfl_sync(0xffffffffu, s1, k - 32);
    return g_srcs[base + k];
}

__device__ __forceinline__ void h2f8(uint4 u, float4& a0, float4& a1) {
    float2 f0 = __half22float2(*(__half2*)&u.x);
    float2 f1 = __half22float2(*(__half2*)&u.y);
    float2 f2 = __half22float2(*(__half2*)&u.z);
    float2 f3 = __half22float2(*(__half2*)&u.w);
    a0 = make_float4(f0.x, f0.y, f1.x, f1.y);
    a1 = make_float4(f2.x, f2.y, f3.x, f3.y);
}

__global__ void __launch_bounds__(256) k_agg(
    const float* __restrict__ att,
    const float* __restrict__ bias)
{
    int w = blockIdx.x * 8 + (threadIdx.x >> 5);
    if (w >= MROWS) return;
    int lane = threadIdx.x & 31;
    int n = w % NN;
    int t = w / NN;
    int f4 = lane * 2;

    const float4* xr = (const float4*)&g_xr[w * HC];
    float4 xr0 = xr[f4];
    float4 xr1 = xr[f4 + 1];
    float4 at0 = ((const float4*)att)[f4];
    float4 at1 = ((const float4*)att)[f4 + 1];

    int base = g_rowptr[n];
    int deg = g_rowptr[n + 1] - base;

    int s0 = (lane < deg) ? g_srcs[base + lane] : 0;
    int s1 = (32 + lane < deg) ? g_srcs[base + 32 + lane] : 0;

    float den = 0.f;
    float4 acc0 = make_float4(0.f, 0.f, 0.f, 0.f);
    float4 acc1 = make_float4(0.f, 0.f, 0.f, 0.f);
    const uint4* xlh4 = (const uint4*)g_xlh;
    int xlbase = t * NN * (HC / 8);

    uint4 A, B, C, D;
    if (deg > 0) A = xlh4[xlbase + get_src(0, s0, s1, base) * (HC / 8) + lane];
    if (deg > 1) B = xlh4[xlbase + get_src(1, s0, s1, base) * (HC / 8) + lane];
    if (deg > 2) C = xlh4[xlbase + get_src(2, s0, s1, base) * (HC / 8) + lane];
    if (deg > 3) D = xlh4[xlbase + get_src(3, s0, s1, base) * (HC / 8) + lane];

#define AGG_BODY(u)                                                          \
    {                                                                        \
        float4 a0, a1;                                                       \
        h2f8(u, a0, a1);                                                     \
        float v, p;                                                          \
        v = a0.x + xr0.x; v = fmaxf(v, 0.2f * v); p = v * at0.x;             \
        v = a0.y + xr0.y; v = fmaxf(v, 0.2f * v); p = fmaf(v, at0.y, p);     \
        v = a0.z + xr0.z; v = fmaxf(v, 0.2f * v); p = fmaf(v, at0.z, p);     \
        v = a0.w + xr0.w; v = fmaxf(v, 0.2f * v); p = fmaf(v, at0.w, p);     \
        v = a1.x + xr1.x; v = fmaxf(v, 0.2f * v); p = fmaf(v, at1.x, p);     \
        v = a1.y + xr1.y; v = fmaxf(v, 0.2f * v); p = fmaf(v, at1.y, p);     \
        v = a1.z + xr1.z; v = fmaxf(v, 0.2f * v); p = fmaf(v, at1.z, p);     \
        v = a1.w + xr1.w; v = fmaxf(v, 0.2f * v); p = fmaf(v, at1.w, p);     \
        p += __shfl_xor_sync(0xffffffffu, p, 1);                             \
        p += __shfl_xor_sync(0xffffffffu, p, 2);                             \
        p += __shfl_xor_sync(0xffffffffu, p, 4);                             \
        float e = __expf(p);                                                 \
        den += e;                                                            \
        acc0.x = fmaf(e, a0.x, acc0.x);                                      \
        acc0.y = fmaf(e, a0.y, acc0.y);                                      \
        acc0.z = fmaf(e, a0.z, acc0.z);                                      \
        acc0.w = fmaf(e, a0.w, acc0.w);                                      \
        acc1.x = fmaf(e, a1.x, acc1.x);                                      \
        acc1.y = fmaf(e, a1.y, acc1.y);                                      \
        acc1.z = fmaf(e, a1.z, acc1.z);                                      \
        acc1.w = fmaf(e, a1.w, acc1.w);                                      \
    }

#define AGG_STEP(R)                                                          \
    {                                                                        \
        uint4 u = R;                                                         \
        if (k + 4 < deg)                                                     \
            R = xlh4[xlbase + get_src(k + 4, s0, s1, base) * (HC / 8) + lane]; \
        AGG_BODY(u);                                                         \
        k++;                                                                 \
    }

    int k = 0;
    while (k < deg) {
        AGG_STEP(A);
        if (k >= deg) break;
        AGG_STEP(B);
        if (k >= deg) break;
        AGG_STEP(C);
        if (k >= deg) break;
        AGG_STEP(D);
    }
#undef AGG_STEP
#undef AGG_BODY

    float inv = (deg > 0) ? 1.0f / den : 0.f;
    const float4* b4 = (const float4*)bias;
    float4 bb0 = b4[f4], bb1 = b4[f4 + 1];
    float4 o0, o1;
    o0.x = fmaxf(fmaf(acc0.x, inv, bb0.x), 0.f);
    o0.y = fmaxf(fmaf(acc0.y, inv, bb0.y), 0.f);
    o0.z = fmaxf(fmaf(acc0.z, inv, bb0.z), 0.f);
    o0.w = fmaxf(fmaf(acc0.w, inv, bb0.w), 0.f);
    o1.x = fmaxf(fmaf(acc1.x, inv, bb1.x), 0.f);
    o1.y = fmaxf(fmaf(acc1.y, inv, bb1.y), 0.f);
    o1.z = fmaxf(fmaf(acc1.z, inv, bb1.z), 0.f);
    o1.w = fmaxf(fmaf(acc1.w, inv, bb1.w), 0.f);
    float4* mo = (float4*)&g_mha[w * HC];
    mo[f4] = o0;
    mo[f4 + 1] = o1;
}

// Tiled projection (256 -> 64) + residual + LayerNorm + relu.
__global__ void __launch_bounds__(256) k_proj(
    const float* __restrict__ x,
    const float* __restrict__ Wp, const float* __restrict__ bp,
    const float* __restrict__ gam, const float* __restrict__ bet,
    float* __restrict__ out)
{
    __shared__ __align__(16) float xs[32][HC];
    __shared__ __align__(16) float ys[32][CO];
    int tid = threadIdx.x;
    int row0 = blockIdx.x * 32;

    {
        const float4* src = (const float4*)&g_mha[row0 * HC];
        float4* dst = (float4*)&xs[0][0];
#pragma unroll
        for (int i = 0; i < 8; i++) dst[tid + i * 256] = src[tid + i * 256];
    }
    __syncthreads();

    int c = tid & 63;
    int rg = tid >> 6;
    float acc[8];
#pragma unroll
    for (int r = 0; r < 8; r++) acc[r] = 0.f;
#pragma unroll 4
    for (int k = 0; k < HC; k++) {
        float w = Wp[k * CO + c];
#pragma unroll
        for (int r = 0; r < 8; r++) {
            acc[r] = fmaf(xs[rg * 8 + r][k], w, acc[r]);
        }
    }
    float bpc = bp[c];
#pragma unroll
    for (int r = 0; r < 8; r++) {
        int row = rg * 8 + r;
        ys[row][c] = acc[r] + bpc + x[(row0 + row) * CC + c];
    }
    __syncthreads();

    int wid = tid >> 5;
    int lane = tid & 31;
    float g0 = gam[lane], g1 = gam[lane + 32];
    float b0 = bet[lane], b1 = bet[lane + 32];
#pragma unroll
    for (int r = 0; r < 4; r++) {
        int row = wid * 4 + r;
        float v0 = ys[row][lane];
        float v1 = ys[row][lane + 32];
        float sv = v0 + v1;
        float sq = v0 * v0 + v1 * v1;
#pragma unroll
        for (int off = 16; off; off >>= 1) {
            sv += __shfl_xor_sync(0xffffffffu, sv, off);
            sq += __shfl_xor_sync(0xffffffffu, sq, off);
        }
        float mu = sv * (1.f / 64.f);
        float var = sq * (1.f / 64.f) - mu * mu;
        float rstd = rsqrtf(var + 1e-5f);
        float y0 = (v0 - mu) * rstd * g0 + b0;
        float y1 = (v1 - mu) * rstd * g1 + b1;
        out[(row0 + row) * CC + lane]      = fmaxf(y0, 0.f);
        out[(row0 + row) * CC + lane + 32] = fmaxf(y1, 0.f);
    }
}

extern "C" void kernel_launch(void* const* d_in, const int* in_sizes, int n_in,
                              void* d_out, int out_size) {
    const float* x    = (const float*)d_in[0];
    const int*   ei   = (const int*)d_in[1];
    const float* Wl   = (const float*)d_in[2];
    const float* bl   = (const float*)d_in[3];
    const float* Wr   = (const float*)d_in[4];
    const float* br   = (const float*)d_in[5];
    const float* att  = (const float*)d_in[6];
    const float* bias = (const float*)d_in[7];
    const float* Wp   = (const float*)d_in[8];
    const float* bp   = (const float*)d_in[9];
    const float* gam  = (const float*)d_in[10];
    const float* bet  = (const float*)d_in[11];
    float* out = (float*)d_out;

    static cudaStream_t s_side = nullptr;
    static cudaEvent_t ev_fork = nullptr, ev_join = nullptr;
    if (!s_side) {
        cudaStreamCreateWithFlags(&s_side, cudaStreamNonBlocking);
        cudaEventCreateWithFlags(&ev_fork, cudaEventDisableTiming);
        cudaEventCreateWithFlags(&ev_join, cudaEventDisableTiming);
        cudaFuncSetAttribute(k_gemm, cudaFuncAttributeMaxDynamicSharedMemorySize,
                             GEMM_SMEM);
    }

    // fork: tensor-core GEMM overlaps the CSR build
    cudaEventRecord(ev_fork, 0);
    cudaStreamWaitEvent(s_side, ev_fork, 0);
    k_gemm<<<(MROWS + 127) / 128, 256, GEMM_SMEM, s_side>>>(x, Wl, bl, Wr, br);
    cudaEventRecord(ev_join, s_side);

    k_hist<<<(EE / 4 + 255) / 256, 256>>>(ei);
    k_scan<<<1, 1024>>>();
    k_scatter<<<(EE / 4 + 255) / 256, 256>>>(ei);

    cudaStreamWaitEvent(0, ev_join, 0);
    k_agg<<<(MROWS + 7) / 8, 256>>>(att, bias);
    k_proj<<<MROWS / 32, 256>>>(x, Wp, bp, gam, bet, out);
}

// round 11
// speedup vs baseline: 1.6129x; 1.2917x over previous
#include <cuda_runtime.h>
#include <cuda_fp16.h>

#define NN 10000
#define TT 2
#define CC 64
#define HH 4
#define CO 64
#define HC 256
#define EE 160000
#define MROWS (TT*NN)

// scratch (static device allocations; no cudaMalloc allowed)
__device__ __half g_xlh[MROWS * HC];   // x_l in fp16 (gathered tensor)
__device__ float  g_xr[MROWS * HC];
__device__ __half g_mhah[MROWS * HC];  // x_mha in fp16
__device__ int    g_deg[NN];           // zero-initialized; k_scan re-zeroes after use
__device__ int    g_rowptr[NN + 1];
__device__ int    g_cursor[NN];
__device__ int    g_srcs[EE];

// 4 edges per thread via int4
__global__ void k_hist(const int* __restrict__ ei) {
    int i = blockIdx.x * blockDim.x + threadIdx.x;
    if (i < EE / 4) {
        int4 d4 = ((const int4*)(ei + EE))[i];
        atomicAdd(&g_deg[d4.x], 1);
        atomicAdd(&g_deg[d4.y], 1);
        atomicAdd(&g_deg[d4.z], 1);
        atomicAdd(&g_deg[d4.w], 1);
    }
}

__global__ void __launch_bounds__(1024) k_scan() {
    __shared__ int sc[1024];
    int tid = threadIdx.x;
    const int CH = (NN + 1023) / 1024;  // 10
    int base = tid * CH;
    int local = 0;
    for (int j = 0; j < CH; j++) {
        int idx = base + j;
        if (idx < NN) local += g_deg[idx];
    }
    sc[tid] = local;
    __syncthreads();
    for (int off = 1; off < 1024; off <<= 1) {
        int v = (tid >= off) ? sc[tid - off] : 0;
        __syncthreads();
        sc[tid] += v;
        __syncthreads();
    }
    int run = sc[tid] - local;  // exclusive prefix
    for (int j = 0; j < CH; j++) {
        int idx = base + j;
        if (idx < NN) {
            int d = g_deg[idx];
            g_rowptr[idx] = run;
            g_cursor[idx] = run;
            run += d;
            g_deg[idx] = 0;   // reset for next invocation (replay-deterministic)
        }
    }
    if (tid == 1023) g_rowptr[NN] = sc[1023];
}

__global__ void k_scatter(const int* __restrict__ ei) {
    int i = blockIdx.x * blockDim.x + threadIdx.x;
    if (i < EE / 4) {
        int4 s4 = ((const int4*)ei)[i];
        int4 d4 = ((const int4*)(ei + EE))[i];
        g_srcs[atomicAdd(&g_cursor[d4.x], 1)] = s4.x;
        g_srcs[atomicAdd(&g_cursor[d4.y], 1)] = s4.y;
        g_srcs[atomicAdd(&g_cursor[d4.z], 1)] = s4.z;
        g_srcs[atomicAdd(&g_cursor[d4.w], 1)] = s4.w;
    }
}

// ================= Tensor-core dual GEMM =================
#define XS_STRIDE 72
#define GEMM_SMEM ((128 * XS_STRIDE + 512 * XS_STRIDE) * 2)

__device__ __forceinline__ unsigned ldsm(const __half* p) {
    return *(const unsigned*)p;
}

__device__ __forceinline__ void mma16816(float* d, const unsigned* a,
                                         unsigned b0, unsigned b1) {
    asm volatile(
        "mma.sync.aligned.m16n8k16.row.col.f32.f16.f16.f32 "
        "{%0,%1,%2,%3}, {%4,%5,%6,%7}, {%8,%9}, {%0,%1,%2,%3};\n"
        : "+f"(d[0]), "+f"(d[1]), "+f"(d[2]), "+f"(d[3])
        : "r"(a[0]), "r"(a[1]), "r"(a[2]), "r"(a[3]), "r"(b0), "r"(b1));
}

__global__ void __launch_bounds__(256) k_gemm(
    const float* __restrict__ x,
    const float* __restrict__ Wl, const float* __restrict__ bl,
    const float* __restrict__ Wr, const float* __restrict__ br)
{
    extern __shared__ __half smem[];
    __half* xs = smem;                       // [128][72]
    __half* Wt = smem + 128 * XS_STRIDE;     // [512][72]

    int tid = threadIdx.x;
    int row0 = blockIdx.x * 128;

#pragma unroll
    for (int it = 0; it < 32; it++) {
        int flat = it * 256 + tid;
        int r = flat >> 6, c = flat & 63;
        int grow = row0 + r;
        float v = (grow < MROWS) ? x[grow * CC + c] : 0.f;
        xs[r * XS_STRIDE + c] = __float2half(v);
    }
#pragma unroll
    for (int it = 0; it < 128; it++) {
        int flat = it * 256 + tid;
        int k = flat >> 9, n = flat & 511;
        float v = (n < HC) ? Wl[k * HC + n] : Wr[k * HC + (n - HC)];
        Wt[n * XS_STRIDE + k] = __float2half(v);
    }
    __syncthreads();

    int lane = tid & 31;
    int wid = tid >> 5;
    int g = lane >> 2;
    int q = lane & 3;
    int wm = wid * 16;

    unsigned Areg[4][4];
#pragma unroll
    for (int ks = 0; ks < 4; ks++) {
        int kb = ks * 16 + q * 2;
        Areg[ks][0] = ldsm(&xs[(wm + g) * XS_STRIDE + kb]);
        Areg[ks][1] = ldsm(&xs[(wm + g + 8) * XS_STRIDE + kb]);
        Areg[ks][2] = ldsm(&xs[(wm + g) * XS_STRIDE + kb + 8]);
        Areg[ks][3] = ldsm(&xs[(wm + g + 8) * XS_STRIDE + kb + 8]);
    }

    int row_lo = row0 + wm + g;
    int row_hi = row_lo + 8;

#pragma unroll 1
    for (int chunk = 0; chunk < 8; chunk++) {
        float d[8][4];
#pragma unroll
        for (int nt = 0; nt < 8; nt++)
#pragma unroll
            for (int e = 0; e < 4; e++) d[nt][e] = 0.f;

#pragma unroll
        for (int ks = 0; ks < 4; ks++) {
            int kb = ks * 16 + q * 2;
#pragma unroll
            for (int nt = 0; nt < 8; nt++) {
                int n = chunk * 64 + nt * 8 + g;
                unsigned b0 = ldsm(&Wt[n * XS_STRIDE + kb]);
                unsigned b1 = ldsm(&Wt[n * XS_STRIDE + kb + 8]);
                mma16816(d[nt], Areg[ks], b0, b1);
            }
        }

#pragma unroll
        for (int nt = 0; nt < 8; nt++) {
            int colg = chunk * 64 + nt * 8 + q * 2;
            if (colg < HC) {
                float b0v = bl[colg], b1v = bl[colg + 1];
                if (row_lo < MROWS) {
                    __half2 h = __floats2half2_rn(d[nt][0] + b0v, d[nt][1] + b1v);
                    *(__half2*)&g_xlh[row_lo * HC + colg] = h;
                }
                if (row_hi < MROWS) {
                    __half2 h = __floats2half2_rn(d[nt][2] + b0v, d[nt][3] + b1v);
                    *(__half2*)&g_xlh[row_hi * HC + colg] = h;
                }
            } else {
                int c = colg - HC;
                float b0v = br[c], b1v = br[c + 1];
                if (row_lo < MROWS) {
                    float2 f = make_float2(d[nt][0] + b0v, d[nt][1] + b1v);
                    *(float2*)&g_xr[row_lo * HC + c] = f;
                }
                if (row_hi < MROWS) {
                    float2 f = make_float2(d[nt][2] + b0v, d[nt][3] + b1v);
                    *(float2*)&g_xr[row_hi * HC + c] = f;
                }
            }
        }
    }
}

// GAT aggregation: one WARP per (t, n). Range [woff, wend) for stream split.
__device__ __forceinline__ int get_src(int k, int s0, int s1, int base) {
    if (k < 32) return __shfl_sync(0xffffffffu, s0, k);
    if (k < 64) return __shfl_sync(0xffffffffu, s1, k - 32);
    return g_srcs[base + k];
}

__device__ __forceinline__ void h2f8(uint4 u, float4& a0, float4& a1) {
    float2 f0 = __half22float2(*(__half2*)&u.x);
    float2 f1 = __half22float2(*(__half2*)&u.y);
    float2 f2 = __half22float2(*(__half2*)&u.z);
    float2 f3 = __half22float2(*(__half2*)&u.w);
    a0 = make_float4(f0.x, f0.y, f1.x, f1.y);
    a1 = make_float4(f2.x, f2.y, f3.x, f3.y);
}

__global__ void __launch_bounds__(256) k_agg(
    const float* __restrict__ att,
    const float* __restrict__ bias,
    int woff, int wend)
{
    int w = woff + blockIdx.x * 8 + (threadIdx.x >> 5);
    if (w >= wend) return;
    int lane = threadIdx.x & 31;
    int n = w % NN;
    int t = w / NN;
    int f4 = lane * 2;

    const float4* xr = (const float4*)&g_xr[w * HC];
    float4 xr0 = xr[f4];
    float4 xr1 = xr[f4 + 1];
    float4 at0 = ((const float4*)att)[f4];
    float4 at1 = ((const float4*)att)[f4 + 1];

    int base = g_rowptr[n];
    int deg = g_rowptr[n + 1] - base;

    int s0 = (lane < deg) ? g_srcs[base + lane] : 0;
    int s1 = (32 + lane < deg) ? g_srcs[base + 32 + lane] : 0;

    float den = 0.f;
    float4 acc0 = make_float4(0.f, 0.f, 0.f, 0.f);
    float4 acc1 = make_float4(0.f, 0.f, 0.f, 0.f);
    const uint4* xlh4 = (const uint4*)g_xlh;
    int xlbase = t * NN * (HC / 8);

    uint4 A, B, C, D;
    if (deg > 0) A = xlh4[xlbase + get_src(0, s0, s1, base) * (HC / 8) + lane];
    if (deg > 1) B = xlh4[xlbase + get_src(1, s0, s1, base) * (HC / 8) + lane];
    if (deg > 2) C = xlh4[xlbase + get_src(2, s0, s1, base) * (HC / 8) + lane];
    if (deg > 3) D = xlh4[xlbase + get_src(3, s0, s1, base) * (HC / 8) + lane];

#define AGG_BODY(u)                                                          \
    {                                                                        \
        float4 a0, a1;                                                       \
        h2f8(u, a0, a1);                                                     \
        float v, p;                                                          \
        v = a0.x + xr0.x; v = fmaxf(v, 0.2f * v); p = v * at0.x;             \
        v = a0.y + xr0.y; v = fmaxf(v, 0.2f * v); p = fmaf(v, at0.y, p);     \
        v = a0.z + xr0.z; v = fmaxf(v, 0.2f * v); p = fmaf(v, at0.z, p);     \
        v = a0.w + xr0.w; v = fmaxf(v, 0.2f * v); p = fmaf(v, at0.w, p);     \
        v = a1.x + xr1.x; v = fmaxf(v, 0.2f * v); p = fmaf(v, at1.x, p);     \
        v = a1.y + xr1.y; v = fmaxf(v, 0.2f * v); p = fmaf(v, at1.y, p);     \
        v = a1.z + xr1.z; v = fmaxf(v, 0.2f * v); p = fmaf(v, at1.z, p);     \
        v = a1.w + xr1.w; v = fmaxf(v, 0.2f * v); p = fmaf(v, at1.w, p);     \
        p += __shfl_xor_sync(0xffffffffu, p, 1);                             \
        p += __shfl_xor_sync(0xffffffffu, p, 2);                             \
        p += __shfl_xor_sync(0xffffffffu, p, 4);                             \
        float e = __expf(p);                                                 \
        den += e;                                                            \
        acc0.x = fmaf(e, a0.x, acc0.x);                                      \
        acc0.y = fmaf(e, a0.y, acc0.y);                                      \
        acc0.z = fmaf(e, a0.z, acc0.z);                                      \
        acc0.w = fmaf(e, a0.w, acc0.w);                                      \
        acc1.x = fmaf(e, a1.x, acc1.x);                                      \
        acc1.y = fmaf(e, a1.y, acc1.y);                                      \
        acc1.z = fmaf(e, a1.z, acc1.z);                                      \
        acc1.w = fmaf(e, a1.w, acc1.w);                                      \
    }

#define AGG_STEP(R)                                                          \
    {                                                                        \
        uint4 u = R;                                                         \
        if (k + 4 < deg)                                                     \
            R = xlh4[xlbase + get_src(k + 4, s0, s1, base) * (HC / 8) + lane]; \
        AGG_BODY(u);                                                         \
        k++;                                                                 \
    }

    int k = 0;
    while (k < deg) {
        AGG_STEP(A);
        if (k >= deg) break;
        AGG_STEP(B);
        if (k >= deg) break;
        AGG_STEP(C);
        if (k >= deg) break;
        AGG_STEP(D);
    }
#undef AGG_STEP
#undef AGG_BODY

    float inv = (deg > 0) ? 1.0f / den : 0.f;
    const float4* b4 = (const float4*)bias;
    float4 bb0 = b4[f4], bb1 = b4[f4 + 1];
    float o0, o1, o2, o3, o4, o5, o6, o7;
    o0 = fmaxf(fmaf(acc0.x, inv, bb0.x), 0.f);
    o1 = fmaxf(fmaf(acc0.y, inv, bb0.y), 0.f);
    o2 = fmaxf(fmaf(acc0.z, inv, bb0.z), 0.f);
    o3 = fmaxf(fmaf(acc0.w, inv, bb0.w), 0.f);
    o4 = fmaxf(fmaf(acc1.x, inv, bb1.x), 0.f);
    o5 = fmaxf(fmaf(acc1.y, inv, bb1.y), 0.f);
    o6 = fmaxf(fmaf(acc1.z, inv, bb1.z), 0.f);
    o7 = fmaxf(fmaf(acc1.w, inv, bb1.w), 0.f);
    __half2 h0 = __floats2half2_rn(o0, o1);
    __half2 h1 = __floats2half2_rn(o2, o3);
    __half2 h2 = __floats2half2_rn(o4, o5);
    __half2 h3 = __floats2half2_rn(o6, o7);
    uint4 pk;
    pk.x = *(unsigned*)&h0; pk.y = *(unsigned*)&h1;
    pk.z = *(unsigned*)&h2; pk.w = *(unsigned*)&h3;
    ((uint4*)g_mhah)[w * (HC / 8) + lane] = pk;
}

// ============ Tensor-core projection + residual + LayerNorm + relu ============
// 64 rows/block, 8 warps = 4 m-tiles x 2 n-halves. x_mha fp16 in, HMMA, LN epilogue.
#define PJ_STRIDE 264
#define PROJ_SMEM ((64 * PJ_STRIDE + 64 * PJ_STRIDE) * 2)

__global__ void __launch_bounds__(256) k_proj(
    const float* __restrict__ x,
    const float* __restrict__ Wp, const float* __restrict__ bp,
    const float* __restrict__ gam, const float* __restrict__ bet,
    float* __restrict__ out, int rbase, int rlim)
{
    extern __shared__ __half psm[];
    __half* xs = psm;                      // [64][264]
    __half* Wt = psm + 64 * PJ_STRIDE;     // [64 n][264 k]
    float* ys = (float*)psm;               // [64][68], aliases xs after MMA

    int tid = threadIdx.x;
    int row0 = rbase + blockIdx.x * 64;

    // load x_mha tile (fp16, 8 halves per uint4)
    const uint4* src = (const uint4*)g_mhah;
#pragma unroll
    for (int it = 0; it < 8; it++) {
        int flat = it * 256 + tid;          // 64 rows * 32 u4
        int r = flat >> 5, u = flat & 31;
        int grow = row0 + r;
        uint4 v = make_uint4(0u, 0u, 0u, 0u);
        if (grow < rlim) v = src[grow * (HC / 8) + u];
        *(uint4*)&xs[r * PJ_STRIDE + u * 8] = v;
    }
    // load Wp^T (n-major)
#pragma unroll
    for (int it = 0; it < 64; it++) {
        int flat = it * 256 + tid;          // 256k * 64n
        int k = flat >> 6, n = flat & 63;
        Wt[n * PJ_STRIDE + k] = __float2half(Wp[k * CO + n]);
    }
    __syncthreads();

    int lane = tid & 31, wid = tid >> 5;
    int g = lane >> 2, q = lane & 3;
    int wm = (wid & 3) * 16;
    int nh = (wid >> 2) * 32;

    float d[4][4];
#pragma unroll
    for (int nt = 0; nt < 4; nt++)
#pragma unroll
        for (int e = 0; e < 4; e++) d[nt][e] = 0.f;

#pragma unroll 4
    for (int ks = 0; ks < 16; ks++) {
        int kb = ks * 16 + q * 2;
        unsigned a[4];
        a[0] = ldsm(&xs[(wm + g) * PJ_STRIDE + kb]);
        a[1] = ldsm(&xs[(wm + g + 8) * PJ_STRIDE + kb]);
        a[2] = ldsm(&xs[(wm + g) * PJ_STRIDE + kb + 8]);
        a[3] = ldsm(&xs[(wm + g + 8) * PJ_STRIDE + kb + 8]);
#pragma unroll
        for (int nt = 0; nt < 4; nt++) {
            int n = nh + nt * 8 + g;
            unsigned b0 = ldsm(&Wt[n * PJ_STRIDE + kb]);
            unsigned b1 = ldsm(&Wt[n * PJ_STRIDE + kb + 8]);
            mma16816(d[nt], a, b0, b1);
        }
    }
    __syncthreads();   // xs reads done; safe to alias ys

    // epilogue: + bp + residual x -> ys
#pragma unroll
    for (int nt = 0; nt < 4; nt++) {
        int c = nh + nt * 8 + q * 2;
        float b0v = bp[c], b1v = bp[c + 1];
        int rl = wm + g, rh = wm + g + 8;
        int gl = row0 + rl, gh = row0 + rh;
        if (gl < rlim) {
            ys[rl * 68 + c]     = d[nt][0] + b0v + x[gl * CC + c];
            ys[rl * 68 + c + 1] = d[nt][1] + b1v + x[gl * CC + c + 1];
        }
        if (gh < rlim) {
            ys[rh * 68 + c]     = d[nt][2] + b0v + x[gh * CC + c];
            ys[rh * 68 + c + 1] = d[nt][3] + b1v + x[gh * CC + c + 1];
        }
    }
    __syncthreads();

    // LayerNorm + relu: warp wid handles rows wid*8 .. wid*8+7
    float g0 = gam[lane], g1 = gam[lane + 32];
    float b0 = bet[lane], b1 = bet[lane + 32];
#pragma unroll
    for (int r = 0; r < 8; r++) {
        int row = wid * 8 + r;
        int grow = row0 + row;
        if (grow >= rlim) break;
        float v0 = ys[row * 68 + lane];
        float v1 = ys[row * 68 + lane + 32];
        float sv = v0 + v1;
        float sq = v0 * v0 + v1 * v1;
#pragma unroll
        for (int off = 16; off; off >>= 1) {
            sv += __shfl_xor_sync(0xffffffffu, sv, off);
            sq += __shfl_xor_sync(0xffffffffu, sq, off);
        }
        float mu = sv * (1.f / 64.f);
        float var = sq * (1.f / 64.f) - mu * mu;
        float rstd = rsqrtf(var + 1e-5f);
        float y0 = (v0 - mu) * rstd * g0 + b0;
        float y1 = (v1 - mu) * rstd * g1 + b1;
        out[grow * CC + lane]      = fmaxf(y0, 0.f);
        out[grow * CC + lane + 32] = fmaxf(y1, 0.f);
    }
}

extern "C" void kernel_launch(void* const* d_in, const int* in_sizes, int n_in,
                              void* d_out, int out_size) {
    const float* x    = (const float*)d_in[0];
    const int*   ei   = (const int*)d_in[1];
    const float* Wl   = (const float*)d_in[2];
    const float* bl   = (const float*)d_in[3];
    const float* Wr   = (const float*)d_in[4];
    const float* br   = (const float*)d_in[5];
    const float* att  = (const float*)d_in[6];
    const float* bias = (const float*)d_in[7];
    const float* Wp   = (const float*)d_in[8];
    const float* bp   = (const float*)d_in[9];
    const float* gam  = (const float*)d_in[10];
    const float* bet  = (const float*)d_in[11];
    float* out = (float*)d_out;

    static cudaStream_t s_side = nullptr;
    static cudaEvent_t ev_fork = nullptr, ev_join = nullptr;
    static cudaEvent_t ev_csr = nullptr, ev_done = nullptr;
    if (!s_side) {
        cudaStreamCreateWithFlags(&s_side, cudaStreamNonBlocking);
        cudaEventCreateWithFlags(&ev_fork, cudaEventDisableTiming);
        cudaEventCreateWithFlags(&ev_join, cudaEventDisableTiming);
        cudaEventCreateWithFlags(&ev_csr, cudaEventDisableTiming);
        cudaEventCreateWithFlags(&ev_done, cudaEventDisableTiming);
        cudaFuncSetAttribute(k_gemm, cudaFuncAttributeMaxDynamicSharedMemorySize,
                             GEMM_SMEM);
        cudaFuncSetAttribute(k_proj, cudaFuncAttributeMaxDynamicSharedMemorySize,
                             PROJ_SMEM);
    }

    // fork: tensor-core GEMM on side overlaps CSR build on main
    cudaEventRecord(ev_fork, 0);
    cudaStreamWaitEvent(s_side, ev_fork, 0);
    k_gemm<<<(MROWS + 127) / 128, 256, GEMM_SMEM, s_side>>>(x, Wl, bl, Wr, br);
    cudaEventRecord(ev_join, s_side);

    k_hist<<<(EE / 4 + 255) / 256, 256>>>(ei);
    k_scan<<<1, 1024>>>();
    k_scatter<<<(EE / 4 + 255) / 256, 256>>>(ei);
    cudaEventRecord(ev_csr, 0);

    // side stream: t=1 half (needs gemm [in-order] + CSR [event])
    cudaStreamWaitEvent(s_side, ev_csr, 0);
    k_agg<<<(NN + 7) / 8, 256, 0, s_side>>>(att, bias, NN, MROWS);
    k_proj<<<(NN + 63) / 64, 256, PROJ_SMEM, s_side>>>(
        x, Wp, bp, gam, bet, out, NN, MROWS);
    cudaEventRecord(ev_done, s_side);

    // main stream: t=0 half (needs gemm via ev_join; CSR in-order)
    cudaStreamWaitEvent(0, ev_join, 0);
    k_agg<<<(NN + 7) / 8, 256>>>(att, bias, 0, NN);
    k_proj<<<(NN + 63) / 64, 256, PROJ_SMEM>>>(x, Wp, bp, gam, bet, out, 0, NN);

    cudaStreamWaitEvent(0, ev_done, 0);
}